// round 15
// baseline (speedup 1.0000x reference)
#include <cuda_runtime.h>
#include <cuda_fp16.h>
#include <cstdint>
#include <math.h>

// Problem constants (FlaxGrok1SparseMoeBlock: B=2,S=1024 -> T=2048, H=1024, I=4096, E=8, K=2)
#define T_TOKENS 2048
#define HDIM 1024
#define IDIM 4096
#define NEXP 8
#define NPAIR (T_TOKENS * 2)

// ---------------- device scratch (static; no runtime allocation) ----------------
__device__ int    d_counts[NEXP];
__device__ int    d_offsets[NEXP];
__device__ int    d_cursor[NEXP];
__device__ int    d_tok[NPAIR];
__device__ float  d_wt[NPAIR];
__device__ int    d_te[NPAIR];
__device__ float  d_tw[NPAIR];
__device__ __align__(16) __half d_act_h[(size_t)NPAIR * IDIM];   // 32 MB (half)
__device__ __align__(16) __half d_x_h[(size_t)T_TOKENS * HDIM];  // 4 MB fp16 x

// ---------------- helpers ----------------
__device__ __forceinline__ uint32_t smem_u32(const void* p) {
    uint32_t a;
    asm("{ .reg .u64 t; cvta.to.shared.u64 t, %1; cvt.u32.u64 %0, t; }" : "=r"(a) : "l"(p));
    return a;
}
__device__ __forceinline__ uint32_t packh2(float lo, float hi) {
    __half2 h = __floats2half2_rn(lo, hi);
    return *(uint32_t*)&h;
}
__device__ __forceinline__ void mma_f16(float c[4], const uint32_t a[4], const uint32_t b[2]) {
    asm volatile(
        "mma.sync.aligned.m16n8k16.row.col.f32.f16.f16.f32 "
        "{%0,%1,%2,%3}, {%4,%5,%6,%7}, {%8,%9}, {%0,%1,%2,%3};"
        : "+f"(c[0]), "+f"(c[1]), "+f"(c[2]), "+f"(c[3])
        : "r"(a[0]), "r"(a[1]), "r"(a[2]), "r"(a[3]), "r"(b[0]), "r"(b[1]));
}
__device__ __forceinline__ void cp16(uint32_t smem_addr, const void* gmem) {
    asm volatile("cp.async.cg.shared.global [%0], [%1], 16;" :: "r"(smem_addr), "l"(gmem));
}
#define CP_COMMIT() asm volatile("cp.async.commit_group;" ::: "memory")
#define CP_WAIT1()  asm volatile("cp.async.wait_group 1;" ::: "memory")
__device__ __forceinline__ float gelu_tanh(float g) {
    float c = g + 0.044715f * g * g * g;
    return 0.5f * g * (1.f + tanhf(0.7978845608028654f * c));
}

// ---------------- kernel 0: zero output + expert counters (fused) ----------------
__global__ void k_init(float* __restrict__ out) {
    size_t i = (size_t)blockIdx.x * 256 + threadIdx.x;
    float4 z = {0.f, 0.f, 0.f, 0.f};
    *(float4*)(out + i * 4) = z;
    if (blockIdx.x == 0 && threadIdx.x < NEXP) d_counts[threadIdx.x] = 0;
}

// ---------------- pre-pass: x fp32 -> fp16 (bit-identical to in-kernel cvt) ----------------
__global__ void k_cvt_x(const float* __restrict__ x) {
    size_t i = (size_t)blockIdx.x * 256 + threadIdx.x;
    float4 v = *(const float4*)(x + i * 4);
    uint2 o; o.x = packh2(v.x, v.y); o.y = packh2(v.z, v.w);
    ((uint2*)d_x_h)[i] = o;
}

// ---------------- kernel 1: router ----------------
__global__ void k_router(const float* __restrict__ x, const float* __restrict__ Wg,
                         float* __restrict__ logits_out) {
    const int t = blockIdx.x;
    const int tid = threadIdx.x;
    const float* xr = x + (size_t)t * HDIM;
    float acc[NEXP];
#pragma unroll
    for (int e = 0; e < NEXP; e++) acc[e] = 0.f;
    for (int h = tid; h < HDIM; h += 256) {
        float xv = xr[h];
#pragma unroll
        for (int e = 0; e < NEXP; e++) acc[e] += xv * Wg[h * NEXP + e];
    }
    __shared__ float red[256];
    __shared__ float lg[NEXP];
#pragma unroll
    for (int e = 0; e < NEXP; e++) {
        red[tid] = acc[e];
        __syncthreads();
        for (int s = 128; s > 0; s >>= 1) { if (tid < s) red[tid] += red[tid + s]; __syncthreads(); }
        if (tid == 0) lg[e] = red[0];
        __syncthreads();
    }
    if (tid == 0) {
        int e0 = 0; float l0 = lg[0];
#pragma unroll
        for (int e = 1; e < NEXP; e++) if (lg[e] > l0) { l0 = lg[e]; e0 = e; }
        int e1 = -1; float l1 = -3.4e38f;
#pragma unroll
        for (int e = 0; e < NEXP; e++) if (e != e0 && lg[e] > l1) { l1 = lg[e]; e1 = e; }
        float tt = expf(l1 - l0);
        float w0 = 1.f / (1.f + tt), w1 = tt / (1.f + tt);
        d_te[2 * t] = e0;     d_tw[2 * t] = w0;
        d_te[2 * t + 1] = e1; d_tw[2 * t + 1] = w1;
        atomicAdd(&d_counts[e0], 1);
        atomicAdd(&d_counts[e1], 1);
        if (logits_out) {
#pragma unroll
            for (int e = 0; e < NEXP; e++) logits_out[(size_t)t * NEXP + e] = lg[e];
        }
    }
}

// ---------------- kernel 2: fused scan + scatter (single block) ----------------
__global__ void k_scansc() {
    if (threadIdx.x == 0) {
        int off = 0;
        for (int e = 0; e < NEXP; e++) { d_offsets[e] = off; d_cursor[e] = off; off += d_counts[e]; }
    }
    __syncthreads();
    for (int i = threadIdx.x; i < NPAIR; i += 1024) {
        int e = d_te[i];
        int pos = atomicAdd(&d_cursor[e], 1);
        d_tok[pos] = i >> 1;
        d_wt[pos]  = d_tw[i];
    }
}

// =====================================================================
// GEMM1: A via cp.async fp16 (d_x_h), B via LDG fp32 + cvt + STS
//   BM=128, BN=64 (x2 matrices), BK=32; 256 threads; warp tile 32x32
//   3-stage hybrid pipeline; 2 CTAs/SM
//   smem stage (u32): A[128][20]=2560, Bg[16][72]=1152, Bv=1152 -> 4864
// =====================================================================
#define NCH1 32
#define G1_STG 4864
#define G1_BG  2560
#define G1_BV  3712
#define SM1_BYTES (3 * G1_STG * 4)

__global__ __launch_bounds__(256, 2)
void k_gemm1(const float* __restrict__ Win, const float* __restrict__ Wv) {
    extern __shared__ uint32_t sm[];
    const uint32_t smb = smem_u32(sm);
    const int e = blockIdx.z;
    const int cnt = d_counts[e];
    const int m0 = blockIdx.y * 128;
    if (m0 >= cnt) return;
    const int n0 = blockIdx.x * 64;
    const int base = d_offsets[e];
    const int tid = threadIdx.x, lane = tid & 31, wid = tid >> 5;
    const int gid = lane >> 2, t4 = lane & 3;
    const int wm = (wid & 3) * 32, wn = (wid >> 2) * 32;

    // A fill (cp.async from fp16 x)
    const int arow = tid >> 1, khalf = tid & 1;
    int gm_a = m0 + arow;
    const __half* xrow = d_x_h + (size_t)d_tok[base + (gm_a < cnt ? gm_a : cnt - 1)] * HDIM + khalf * 16;
    const uint32_t sA = (uint32_t)(arow * 20 + khalf * 8) * 4;
    // B fill (fp32 LDG + cvt + STS)
    const int kp = tid >> 4;               // 0..15
    const int nb4 = (tid & 15) * 4;        // 0..60
    const float* wg0 = Win + ((size_t)e * HDIM + 2 * kp) * IDIM + n0 + nb4;
    const float* wv0 = Wv  + ((size_t)e * HDIM + 2 * kp) * IDIM + n0 + nb4;

    float4 pG0, pG1, pV0, pV1;

#define FA1(c) do { \
        uint32_t st_ = smb + ((c) % 3) * (G1_STG * 4); \
        const __half* a_ = xrow + (c) * 32; \
        cp16(st_ + sA, a_); \
        cp16(st_ + sA + 16, a_ + 8); \
        CP_COMMIT(); \
    } while (0)
#define LB1(c) do { \
        const float* g_ = wg0 + (size_t)(c) * 32 * IDIM; \
        pG0 = *(const float4*)(g_); pG1 = *(const float4*)(g_ + IDIM); \
        const float* v_ = wv0 + (size_t)(c) * 32 * IDIM; \
        pV0 = *(const float4*)(v_); pV1 = *(const float4*)(v_ + IDIM); \
    } while (0)
#define SB1(s) do { \
        uint32_t* Bg_ = sm + (s) * G1_STG + G1_BG; \
        uint4 tg; tg.x = packh2(pG0.x, pG1.x); tg.y = packh2(pG0.y, pG1.y); \
                  tg.z = packh2(pG0.z, pG1.z); tg.w = packh2(pG0.w, pG1.w); \
        *(uint4*)(Bg_ + kp * 72 + nb4) = tg; \
        uint32_t* Bv_ = sm + (s) * G1_STG + G1_BV; \
        uint4 tv; tv.x = packh2(pV0.x, pV1.x); tv.y = packh2(pV0.y, pV1.y); \
                  tv.z = packh2(pV0.z, pV1.z); tv.w = packh2(pV0.w, pV1.w); \
        *(uint4*)(Bv_ + kp * 72 + nb4) = tv; \
    } while (0)

    float accg[2][4][4], accv[2][4][4];
#pragma unroll
    for (int i = 0; i < 2; i++)
#pragma unroll
        for (int j = 0; j < 4; j++)
#pragma unroll
            for (int q = 0; q < 4; q++) { accg[i][j][q] = 0.f; accv[i][j][q] = 0.f; }

    FA1(0); FA1(1);
    LB1(0); SB1(0); LB1(1);
    __syncthreads();

    for (int c = 0; c < NCH1; c++) {
        CP_WAIT1();                     // A stage c landed (groups every iter keep invariant)
        SB1((c + 1) % 3);               // STS B for stage c+1 (regs from last iter)
        if (c + 2 < NCH1) LB1(c + 2);
        __syncthreads();                // B stage c visible; all warps done with stage c-1
        if (c + 2 < NCH1) FA1(c + 2);   // safe: stage (c+2)%3=(c-1)%3 fully consumed
        else CP_COMMIT();               // tail: keep group accounting
        const uint32_t* A_ = sm + (c % 3) * G1_STG;
        const uint32_t* Bg_ = A_ + G1_BG;
        const uint32_t* Bv_ = A_ + G1_BV;
#pragma unroll
        for (int s = 0; s < 2; s++) {
            uint32_t af[2][4];
#pragma unroll
            for (int mt = 0; mt < 2; mt++) {
                int r = wm + mt * 16 + gid;
                af[mt][0] = A_[r * 20 + s * 8 + t4];
                af[mt][1] = A_[(r + 8) * 20 + s * 8 + t4];
                af[mt][2] = A_[r * 20 + s * 8 + t4 + 4];
                af[mt][3] = A_[(r + 8) * 20 + s * 8 + t4 + 4];
            }
#pragma unroll
            for (int nt = 0; nt < 4; nt++) {
                int cidx = wn + nt * 8 + gid;
                uint32_t bg[2] = { Bg_[(s * 8 + t4) * 72 + cidx], Bg_[(s * 8 + t4 + 4) * 72 + cidx] };
                uint32_t bv[2] = { Bv_[(s * 8 + t4) * 72 + cidx], Bv_[(s * 8 + t4 + 4) * 72 + cidx] };
#pragma unroll
                for (int mt = 0; mt < 2; mt++) {
                    mma_f16(accg[mt][nt], af[mt], bg);
                    mma_f16(accv[mt][nt], af[mt], bv);
                }
            }
        }
    }

    // epilogue: act = gelu(g)*v -> half
#pragma unroll
    for (int mt = 0; mt < 2; mt++) {
#pragma unroll
        for (int nt = 0; nt < 4; nt++) {
            int col = n0 + wn + nt * 8 + t4 * 2;
#pragma unroll
            for (int h = 0; h < 2; h++) {
                int gm = m0 + wm + mt * 16 + gid + h * 8;
                if (gm < cnt) {
                    float a0 = gelu_tanh(accg[mt][nt][h * 2])     * accv[mt][nt][h * 2];
                    float a1 = gelu_tanh(accg[mt][nt][h * 2 + 1]) * accv[mt][nt][h * 2 + 1];
                    *(uint32_t*)(d_act_h + (size_t)(base + gm) * IDIM + col) = packh2(a0, a1);
                }
            }
        }
    }
#undef FA1
#undef LB1
#undef SB1
}

// =====================================================================
// GEMM2: A via cp.async fp16 (d_act_h), B via LDG fp32 + cvt + STS
//   out[token] += (act@Wout[e]) * wt  (fused deterministic atomic combine)
//   BM=128, BN=128, BK=32; 256 threads; warp tile 32x64; 2 CTAs/SM
//   smem stage (u32): A[128][20]=2560, B[16][136]=2176 -> 4736
// =====================================================================
#define NCH2 128
#define G2_STG 4736
#define G2_B   2560
#define SM2_BYTES (3 * G2_STG * 4)

__global__ __launch_bounds__(256, 2)
void k_gemm2(const float* __restrict__ Wout, float* __restrict__ out) {
    extern __shared__ uint32_t sm[];
    const uint32_t smb = smem_u32(sm);
    const int e = blockIdx.z;
    const int cnt = d_counts[e];
    const int m0 = blockIdx.y * 128;
    if (m0 >= cnt) return;
    const int n0 = blockIdx.x * 128;
    const int base = d_offsets[e];
    const int tid = threadIdx.x, lane = tid & 31, wid = tid >> 5;
    const int gid = lane >> 2, t4 = lane & 3;
    const int wm = (wid & 3) * 32, wn = (wid >> 2) * 64;

    const int arow = tid >> 1, khalf = tid & 1;
    int slot_a = base + m0 + arow;
    if (slot_a > NPAIR - 1) slot_a = NPAIR - 1;
    const __half* actrow = d_act_h + (size_t)slot_a * IDIM + khalf * 16;
    const uint32_t sA = (uint32_t)(arow * 20 + khalf * 8) * 4;

    const int kp = tid >> 4;               // 0..15
    const int nb8 = (tid & 15) * 8;        // 0..120
    const float* w0 = Wout + ((size_t)e * IDIM + 2 * kp) * HDIM + n0 + nb8;

    float4 pB00, pB01, pB10, pB11;

#define FA2(c) do { \
        uint32_t st_ = smb + ((c) % 3) * (G2_STG * 4); \
        const __half* a_ = actrow + (c) * 32; \
        cp16(st_ + sA, a_); \
        cp16(st_ + sA + 16, a_ + 8); \
        CP_COMMIT(); \
    } while (0)
#define LB2(c) do { \
        const float* wr_ = w0 + (size_t)(c) * 32 * HDIM; \
        pB00 = *(const float4*)(wr_);        pB01 = *(const float4*)(wr_ + 4); \
        pB10 = *(const float4*)(wr_ + HDIM); pB11 = *(const float4*)(wr_ + HDIM + 4); \
    } while (0)
#define SB2(s) do { \
        uint32_t* B_ = sm + (s) * G2_STG + G2_B; \
        uint4 t0, t1; \
        t0.x = packh2(pB00.x, pB10.x); t0.y = packh2(pB00.y, pB10.y); \
        t0.z = packh2(pB00.z, pB10.z); t0.w = packh2(pB00.w, pB10.w); \
        t1.x = packh2(pB01.x, pB11.x); t1.y = packh2(pB01.y, pB11.y); \
        t1.z = packh2(pB01.z, pB11.z); t1.w = packh2(pB01.w, pB11.w); \
        *(uint4*)(B_ + kp * 136 + nb8)     = t0; \
        *(uint4*)(B_ + kp * 136 + nb8 + 4) = t1; \
    } while (0)

    float acc[2][8][4];
#pragma unroll
    for (int i = 0; i < 2; i++)
#pragma unroll
        for (int j = 0; j < 8; j++)
#pragma unroll
            for (int q = 0; q < 4; q++) acc[i][j][q] = 0.f;

    FA2(0); FA2(1);
    LB2(0); SB2(0); LB2(1);
    __syncthreads();

    for (int c = 0; c < NCH2; c++) {
        CP_WAIT1();
        SB2((c + 1) % 3);
        if (c + 2 < NCH2) LB2(c + 2);
        __syncthreads();
        if (c + 2 < NCH2) FA2(c + 2);
        else CP_COMMIT();
        const uint32_t* A_ = sm + (c % 3) * G2_STG;
        const uint32_t* B_ = A_ + G2_B;
#pragma unroll
        for (int s = 0; s < 2; s++) {
            uint32_t af[2][4];
#pragma unroll
            for (int mt = 0; mt < 2; mt++) {
                int r = wm + mt * 16 + gid;
                af[mt][0] = A_[r * 20 + s * 8 + t4];
                af[mt][1] = A_[(r + 8) * 20 + s * 8 + t4];
                af[mt][2] = A_[r * 20 + s * 8 + t4 + 4];
                af[mt][3] = A_[(r + 8) * 20 + s * 8 + t4 + 4];
            }
#pragma unroll
            for (int nt = 0; nt < 8; nt++) {
                int cidx = wn + nt * 8 + gid;
                uint32_t bf[2] = { B_[(s * 8 + t4) * 136 + cidx], B_[(s * 8 + t4 + 4) * 136 + cidx] };
#pragma unroll
                for (int mt = 0; mt < 2; mt++) mma_f16(acc[mt][nt], af[mt], bf);
            }
        }
    }

    // epilogue: out[token] += acc * wt  (2 deterministic atomic adds per element)
#pragma unroll
    for (int mt = 0; mt < 2; mt++) {
#pragma unroll
        for (int nt = 0; nt < 8; nt++) {
            int col = n0 + wn + nt * 8 + t4 * 2;
#pragma unroll
            for (int h = 0; h < 2; h++) {
                int gm = m0 + wm + mt * 16 + gid + h * 8;
                if (gm < cnt) {
                    float wt = d_wt[base + gm];
                    int token = d_tok[base + gm];
                    float* dst = out + (size_t)token * HDIM + col;
                    atomicAdd(dst,     acc[mt][nt][h * 2]     * wt);
                    atomicAdd(dst + 1, acc[mt][nt][h * 2 + 1] * wt);
                }
            }
        }
    }
#undef FA2
#undef LB2
#undef SB2
}

// ---------------- launch ----------------
extern "C" void kernel_launch(void* const* d_in, const int* in_sizes, int n_in,
                              void* d_out, int out_size) {
    const float* x    = (const float*)d_in[0];
    const float* Wg   = (const float*)d_in[1];
    const float* Win  = (const float*)d_in[2];
    const float* Wv   = (const float*)d_in[3];
    const float* Wout = (const float*)d_in[4];
    float* out = (float*)d_out;

    float* logits = nullptr;
    if (out_size >= (int)((size_t)T_TOKENS * HDIM + (size_t)T_TOKENS * NEXP))
        logits = out + (size_t)T_TOKENS * HDIM;

    cudaFuncSetAttribute(k_gemm1, cudaFuncAttributeMaxDynamicSharedMemorySize, SM1_BYTES);
    cudaFuncSetAttribute(k_gemm2, cudaFuncAttributeMaxDynamicSharedMemorySize, SM2_BYTES);

    k_init<<<(T_TOKENS * HDIM / 4) / 256, 256>>>(out);
    k_cvt_x<<<(T_TOKENS * HDIM / 4) / 256, 256>>>(x);
    k_router<<<T_TOKENS, 256>>>(x, Wg, logits);
    k_scansc<<<1, 1024>>>();

    dim3 g1(IDIM / 64, (T_TOKENS + 127) / 128, NEXP);
    k_gemm1<<<g1, 256, SM1_BYTES>>>(Win, Wv);

    dim3 g2(HDIM / 128, (T_TOKENS + 127) / 128, NEXP);
    k_gemm2<<<g2, 256, SM2_BYTES>>>(Wout, out);
}

// round 16
// speedup vs baseline: 1.0804x; 1.0804x over previous
#include <cuda_runtime.h>
#include <cuda_fp16.h>
#include <cstdint>
#include <math.h>

// Problem constants (FlaxGrok1SparseMoeBlock: B=2,S=1024 -> T=2048, H=1024, I=4096, E=8, K=2)
#define T_TOKENS 2048
#define HDIM 1024
#define IDIM 4096
#define NEXP 8
#define NPAIR (T_TOKENS * 2)

// ---------------- device scratch (static; no runtime allocation) ----------------
__device__ int    d_counts[NEXP];
__device__ int    d_offsets[NEXP];
__device__ int    d_cursor[NEXP];
__device__ int    d_tok[NPAIR];
__device__ float  d_wt[NPAIR];
__device__ int    d_te[NPAIR];
__device__ float  d_tw[NPAIR];
__device__ __align__(16) __half d_act_h[(size_t)NPAIR * IDIM];  // 32 MB (half)

// ---------------- helpers ----------------
__device__ __forceinline__ uint32_t packh2(float lo, float hi) {
    __half2 h = __floats2half2_rn(lo, hi);
    return *(uint32_t*)&h;
}
__device__ __forceinline__ void mma_f16(float c[4], const uint32_t a[4], const uint32_t b[2]) {
    asm volatile(
        "mma.sync.aligned.m16n8k16.row.col.f32.f16.f16.f32 "
        "{%0,%1,%2,%3}, {%4,%5,%6,%7}, {%8,%9}, {%0,%1,%2,%3};"
        : "+f"(c[0]), "+f"(c[1]), "+f"(c[2]), "+f"(c[3])
        : "r"(a[0]), "r"(a[1]), "r"(a[2]), "r"(a[3]), "r"(b[0]), "r"(b[1]));
}
__device__ __forceinline__ float gelu_tanh(float g) {
    float c = g + 0.044715f * g * g * g;
    return 0.5f * g * (1.f + tanhf(0.7978845608028654f * c));
}

// ---------------- kernel 0: zero output + expert counters (fused) ----------------
__global__ void k_init(float* __restrict__ out) {
    size_t i = (size_t)blockIdx.x * 256 + threadIdx.x;
    float4 z = {0.f, 0.f, 0.f, 0.f};
    *(float4*)(out + i * 4) = z;
    if (blockIdx.x == 0 && threadIdx.x < NEXP) d_counts[threadIdx.x] = 0;
}

// ---------------- kernel 1: router, warp-per-token (no block barriers) ----------------
__global__ void k_router(const float* __restrict__ x, const float* __restrict__ Wg,
                         float* __restrict__ logits_out) {
    const int lane = threadIdx.x & 31;
    const int t = blockIdx.x * 8 + (threadIdx.x >> 5);
    const float* xr = x + (size_t)t * HDIM;

    float acc[NEXP];
#pragma unroll
    for (int e = 0; e < NEXP; e++) acc[e] = 0.f;

    for (int h = lane; h < HDIM; h += 32) {
        float xv = xr[h];
        float4 w0 = *(const float4*)(Wg + h * NEXP);
        float4 w1 = *(const float4*)(Wg + h * NEXP + 4);
        acc[0] += xv * w0.x; acc[1] += xv * w0.y; acc[2] += xv * w0.z; acc[3] += xv * w0.w;
        acc[4] += xv * w1.x; acc[5] += xv * w1.y; acc[6] += xv * w1.z; acc[7] += xv * w1.w;
    }
    // warp reductions (butterfly) — every lane ends with the full sums
#pragma unroll
    for (int e = 0; e < NEXP; e++) {
#pragma unroll
        for (int s = 16; s > 0; s >>= 1)
            acc[e] += __shfl_xor_sync(0xffffffffu, acc[e], s);
    }

    if (lane == 0) {
        int e0 = 0; float l0 = acc[0];
#pragma unroll
        for (int e = 1; e < NEXP; e++) if (acc[e] > l0) { l0 = acc[e]; e0 = e; }
        int e1 = -1; float l1 = -3.4e38f;
#pragma unroll
        for (int e = 0; e < NEXP; e++) if (e != e0 && acc[e] > l1) { l1 = acc[e]; e1 = e; }
        float tt = expf(l1 - l0);
        float w0 = 1.f / (1.f + tt), w1 = tt / (1.f + tt);
        d_te[2 * t] = e0;     d_tw[2 * t] = w0;
        d_te[2 * t + 1] = e1; d_tw[2 * t + 1] = w1;
        atomicAdd(&d_counts[e0], 1);
        atomicAdd(&d_counts[e1], 1);
    }
    if (logits_out && lane < NEXP)
        logits_out[(size_t)t * NEXP + lane] = acc[lane];
}

// ---------------- kernel 2: fused scan + scatter (single block) ----------------
__global__ void k_scansc() {
    if (threadIdx.x == 0) {
        int off = 0;
        for (int e = 0; e < NEXP; e++) { d_offsets[e] = off; d_cursor[e] = off; off += d_counts[e]; }
    }
    __syncthreads();
    for (int i = threadIdx.x; i < NPAIR; i += 1024) {
        int e = d_te[i];
        int pos = atomicAdd(&d_cursor[e], 1);
        d_tok[pos] = i >> 1;
        d_wt[pos]  = d_tw[i];
    }
}

// =====================================================================
// GEMM1 (fp16 mma.sync m16n8k16): g=x@Win[e], v=x@Wv[e], act=gelu(g)*v
//   BM=128, BN=64 (per matrix, x2), BK=32; 256 threads; warp tile 32x32
//   3-stage smem pipeline; 2 CTAs/SM  (proven R7/R13 mainloop — frozen)
//   smem stage (u32): A[128][20]=2560, Bg[16][72]=1152, Bv=1152 -> 4864
// =====================================================================
#define NCH1 32
#define G1_STG 4864
#define G1_BG  2560
#define G1_BV  3712
#define SM1_BYTES (3 * G1_STG * 4)

__global__ __launch_bounds__(256, 2)
void k_gemm1(const float* __restrict__ x, const float* __restrict__ Win,
             const float* __restrict__ Wv) {
    extern __shared__ uint32_t sm[];
    const int e = blockIdx.z;
    const int cnt = d_counts[e];
    const int m0 = blockIdx.y * 128;
    if (m0 >= cnt) return;
    const int n0 = blockIdx.x * 64;
    const int base = d_offsets[e];
    const int tid = threadIdx.x, lane = tid & 31, wid = tid >> 5;
    const int gid = lane >> 2, t4 = lane & 3;
    const int wm = (wid & 3) * 32, wn = (wid >> 2) * 32;

    // fill mappings
    const int arow = tid >> 1, khalf = tid & 1;
    int gm_a = m0 + arow;
    const float* xrow = x + (size_t)d_tok[base + (gm_a < cnt ? gm_a : cnt - 1)] * HDIM + khalf * 16;
    const int kp = tid >> 4;               // 0..15
    const int nb4 = (tid & 15) * 4;        // 0..60
    const float* wg0 = Win + ((size_t)e * HDIM + 2 * kp) * IDIM + n0 + nb4;
    const float* wv0 = Wv  + ((size_t)e * HDIM + 2 * kp) * IDIM + n0 + nb4;

    float4 pA[4], pG0, pG1, pV0, pV1;

#define G1_LD(c) do { \
        const float* xr_ = xrow + (c) * 32; \
        pA[0] = *(const float4*)(xr_);      pA[1] = *(const float4*)(xr_ + 4); \
        pA[2] = *(const float4*)(xr_ + 8);  pA[3] = *(const float4*)(xr_ + 12); \
        const float* g_ = wg0 + (size_t)(c) * 32 * IDIM; \
        pG0 = *(const float4*)(g_); pG1 = *(const float4*)(g_ + IDIM); \
        const float* v_ = wv0 + (size_t)(c) * 32 * IDIM; \
        pV0 = *(const float4*)(v_); pV1 = *(const float4*)(v_ + IDIM); \
    } while (0)

#define G1_ST(s) do { \
        uint32_t* A_ = sm + (s) * G1_STG; \
        uint4 ua0, ua1; \
        ua0.x = packh2(pA[0].x, pA[0].y); ua0.y = packh2(pA[0].z, pA[0].w); \
        ua0.z = packh2(pA[1].x, pA[1].y); ua0.w = packh2(pA[1].z, pA[1].w); \
        ua1.x = packh2(pA[2].x, pA[2].y); ua1.y = packh2(pA[2].z, pA[2].w); \
        ua1.z = packh2(pA[3].x, pA[3].y); ua1.w = packh2(pA[3].z, pA[3].w); \
        *(uint4*)(A_ + arow * 20 + khalf * 8)     = ua0; \
        *(uint4*)(A_ + arow * 20 + khalf * 8 + 4) = ua1; \
        uint32_t* Bg_ = sm + (s) * G1_STG + G1_BG; \
        uint4 tg; tg.x = packh2(pG0.x, pG1.x); tg.y = packh2(pG0.y, pG1.y); \
                  tg.z = packh2(pG0.z, pG1.z); tg.w = packh2(pG0.w, pG1.w); \
        *(uint4*)(Bg_ + kp * 72 + nb4) = tg; \
        uint32_t* Bv_ = sm + (s) * G1_STG + G1_BV; \
        uint4 tv; tv.x = packh2(pV0.x, pV1.x); tv.y = packh2(pV0.y, pV1.y); \
                  tv.z = packh2(pV0.z, pV1.z); tv.w = packh2(pV0.w, pV1.w); \
        *(uint4*)(Bv_ + kp * 72 + nb4) = tv; \
    } while (0)

    float accg[2][4][4], accv[2][4][4];
#pragma unroll
    for (int i = 0; i < 2; i++)
#pragma unroll
        for (int j = 0; j < 4; j++)
#pragma unroll
            for (int q = 0; q < 4; q++) { accg[i][j][q] = 0.f; accv[i][j][q] = 0.f; }

    G1_LD(0); G1_ST(0); G1_LD(1);
    __syncthreads();

    for (int c = 0; c < NCH1; c++) {
        if (c + 1 < NCH1) G1_ST((c + 1) % 3);
        if (c + 2 < NCH1) G1_LD(c + 2);
        __syncthreads();
        const uint32_t* A_ = sm + (c % 3) * G1_STG;
        const uint32_t* Bg_ = A_ + G1_BG;
        const uint32_t* Bv_ = A_ + G1_BV;
#pragma unroll
        for (int s = 0; s < 2; s++) {
            uint32_t af[2][4];
#pragma unroll
            for (int mt = 0; mt < 2; mt++) {
                int r = wm + mt * 16 + gid;
                af[mt][0] = A_[r * 20 + s * 8 + t4];
                af[mt][1] = A_[(r + 8) * 20 + s * 8 + t4];
                af[mt][2] = A_[r * 20 + s * 8 + t4 + 4];
                af[mt][3] = A_[(r + 8) * 20 + s * 8 + t4 + 4];
            }
#pragma unroll
            for (int nt = 0; nt < 4; nt++) {
                int cidx = wn + nt * 8 + gid;
                uint32_t bg[2] = { Bg_[(s * 8 + t4) * 72 + cidx], Bg_[(s * 8 + t4 + 4) * 72 + cidx] };
                uint32_t bv[2] = { Bv_[(s * 8 + t4) * 72 + cidx], Bv_[(s * 8 + t4 + 4) * 72 + cidx] };
#pragma unroll
                for (int mt = 0; mt < 2; mt++) {
                    mma_f16(accg[mt][nt], af[mt], bg);
                    mma_f16(accv[mt][nt], af[mt], bv);
                }
            }
        }
    }

    // epilogue: act = gelu(g)*v -> half
#pragma unroll
    for (int mt = 0; mt < 2; mt++) {
#pragma unroll
        for (int nt = 0; nt < 4; nt++) {
            int col = n0 + wn + nt * 8 + t4 * 2;
#pragma unroll
            for (int h = 0; h < 2; h++) {
                int gm = m0 + wm + mt * 16 + gid + h * 8;
                if (gm < cnt) {
                    float a0 = gelu_tanh(accg[mt][nt][h * 2])     * accv[mt][nt][h * 2];
                    float a1 = gelu_tanh(accg[mt][nt][h * 2 + 1]) * accv[mt][nt][h * 2 + 1];
                    *(uint32_t*)(d_act_h + (size_t)(base + gm) * IDIM + col) = packh2(a0, a1);
                }
            }
        }
    }
#undef G1_LD
#undef G1_ST
}

// =====================================================================
// GEMM2 (fp16 mma.sync): out[token] += (act@Wout[e]) * wt  (fused combine)
//   BM=128, BN=128, BK=32; 256 threads; warp tile 32x64; 2 CTAs/SM
//   Exactly 2 atomic contributions per output element; fp32 two-operand
//   addition is commutative -> result is bitwise deterministic. (frozen)
//   smem stage (u32): A[128][20]=2560, B[16][136]=2176 -> 4736
// =====================================================================
#define NCH2 128
#define G2_STG 4736
#define G2_B   2560
#define SM2_BYTES (3 * G2_STG * 4)

__global__ __launch_bounds__(256, 2)
void k_gemm2(const float* __restrict__ Wout, float* __restrict__ out) {
    extern __shared__ uint32_t sm[];
    const int e = blockIdx.z;
    const int cnt = d_counts[e];
    const int m0 = blockIdx.y * 128;
    if (m0 >= cnt) return;
    const int n0 = blockIdx.x * 128;
    const int base = d_offsets[e];
    const int tid = threadIdx.x, lane = tid & 31, wid = tid >> 5;
    const int gid = lane >> 2, t4 = lane & 3;
    const int wm = (wid & 3) * 32, wn = (wid >> 2) * 64;

    const int arow = tid >> 1, khalf = tid & 1;
    int gm_a = m0 + arow;
    int slot_a = base + gm_a;
    if (slot_a > NPAIR - 1) slot_a = NPAIR - 1;
    const __half* actrow = d_act_h + (size_t)slot_a * IDIM + khalf * 16;

    const int kp = tid >> 4;               // 0..15
    const int nb8 = (tid & 15) * 8;        // 0..120
    const float* w0 = Wout + ((size_t)e * IDIM + 2 * kp) * HDIM + n0 + nb8;

    uint4 pA0, pA1;
    float4 pB00, pB01, pB10, pB11;

#define G2_LD(c) do { \
        const __half* ar_ = actrow + (c) * 32; \
        pA0 = *(const uint4*)(ar_); pA1 = *(const uint4*)(ar_ + 8); \
        const float* wr_ = w0 + (size_t)(c) * 32 * HDIM; \
        pB00 = *(const float4*)(wr_);        pB01 = *(const float4*)(wr_ + 4); \
        pB10 = *(const float4*)(wr_ + HDIM); pB11 = *(const float4*)(wr_ + HDIM + 4); \
    } while (0)

#define G2_ST(s) do { \
        uint32_t* A_ = sm + (s) * G2_STG; \
        *(uint4*)(A_ + arow * 20 + khalf * 8)     = pA0; \
        *(uint4*)(A_ + arow * 20 + khalf * 8 + 4) = pA1; \
        uint32_t* B_ = sm + (s) * G2_STG + G2_B; \
        uint4 t0, t1; \
        t0.x = packh2(pB00.x, pB10.x); t0.y = packh2(pB00.y, pB10.y); \
        t0.z = packh2(pB00.z, pB10.z); t0.w = packh2(pB00.w, pB10.w); \
        t1.x = packh2(pB01.x, pB11.x); t1.y = packh2(pB01.y, pB11.y); \
        t1.z = packh2(pB01.z, pB11.z); t1.w = packh2(pB01.w, pB11.w); \
        *(uint4*)(B_ + kp * 136 + nb8)     = t0; \
        *(uint4*)(B_ + kp * 136 + nb8 + 4) = t1; \
    } while (0)

    float acc[2][8][4];
#pragma unroll
    for (int i = 0; i < 2; i++)
#pragma unroll
        for (int j = 0; j < 8; j++)
#pragma unroll
            for (int q = 0; q < 4; q++) acc[i][j][q] = 0.f;

    G2_LD(0); G2_ST(0); G2_LD(1);
    __syncthreads();

    for (int c = 0; c < NCH2; c++) {
        if (c + 1 < NCH2) G2_ST((c + 1) % 3);
        if (c + 2 < NCH2) G2_LD(c + 2);
        __syncthreads();
        const uint32_t* A_ = sm + (c % 3) * G2_STG;
        const uint32_t* B_ = A_ + G2_B;
#pragma unroll
        for (int s = 0; s < 2; s++) {
            uint32_t af[2][4];
#pragma unroll
            for (int mt = 0; mt < 2; mt++) {
                int r = wm + mt * 16 + gid;
                af[mt][0] = A_[r * 20 + s * 8 + t4];
                af[mt][1] = A_[(r + 8) * 20 + s * 8 + t4];
                af[mt][2] = A_[r * 20 + s * 8 + t4 + 4];
                af[mt][3] = A_[(r + 8) * 20 + s * 8 + t4 + 4];
            }
#pragma unroll
            for (int nt = 0; nt < 8; nt++) {
                int cidx = wn + nt * 8 + gid;
                uint32_t bf[2] = { B_[(s * 8 + t4) * 136 + cidx], B_[(s * 8 + t4 + 4) * 136 + cidx] };
#pragma unroll
                for (int mt = 0; mt < 2; mt++) mma_f16(acc[mt][nt], af[mt], bf);
            }
        }
    }

    // epilogue: out[token] += acc * wt  (2 deterministic atomic adds per element)
#pragma unroll
    for (int mt = 0; mt < 2; mt++) {
#pragma unroll
        for (int nt = 0; nt < 8; nt++) {
            int col = n0 + wn + nt * 8 + t4 * 2;
#pragma unroll
            for (int h = 0; h < 2; h++) {
                int gm = m0 + wm + mt * 16 + gid + h * 8;
                if (gm < cnt) {
                    float wt = d_wt[base + gm];
                    int token = d_tok[base + gm];
                    float* dst = out + (size_t)token * HDIM + col;
                    atomicAdd(dst,     acc[mt][nt][h * 2]     * wt);
                    atomicAdd(dst + 1, acc[mt][nt][h * 2 + 1] * wt);
                }
            }
        }
    }
#undef G2_LD
#undef G2_ST
}

// ---------------- launch ----------------
extern "C" void kernel_launch(void* const* d_in, const int* in_sizes, int n_in,
                              void* d_out, int out_size) {
    const float* x    = (const float*)d_in[0];
    const float* Wg   = (const float*)d_in[1];
    const float* Win  = (const float*)d_in[2];
    const float* Wv   = (const float*)d_in[3];
    const float* Wout = (const float*)d_in[4];
    float* out = (float*)d_out;

    float* logits = nullptr;
    if (out_size >= (int)((size_t)T_TOKENS * HDIM + (size_t)T_TOKENS * NEXP))
        logits = out + (size_t)T_TOKENS * HDIM;

    cudaFuncSetAttribute(k_gemm1, cudaFuncAttributeMaxDynamicSharedMemorySize, SM1_BYTES);
    cudaFuncSetAttribute(k_gemm2, cudaFuncAttributeMaxDynamicSharedMemorySize, SM2_BYTES);

    k_init<<<(T_TOKENS * HDIM / 4) / 256, 256>>>(out);
    k_router<<<T_TOKENS / 8, 256>>>(x, Wg, logits);
    k_scansc<<<1, 1024>>>();

    dim3 g1(IDIM / 64, (T_TOKENS + 127) / 128, NEXP);
    k_gemm1<<<g1, 256, SM1_BYTES>>>(x, Win, Wv);

    dim3 g2(HDIM / 128, (T_TOKENS + 127) / 128, NEXP);
    k_gemm2<<<g2, 256, SM2_BYTES>>>(Wout, out);
}